// round 15
// baseline (speedup 1.0000x reference)
#include <cuda_runtime.h>
#include <cstdint>

// Problem constants
#define B_     16
#define L_     1024
#define D_     256
#define PAST_  16
#define LQ_    (L_ - PAST_)   // 1008
#define NL_    3

#define O_ELEMS     ((size_t)B_ * LQ_ * 256)          // 4,128,768 floats
#define ATTN_BYTES  ((size_t)B_ * NL_ * L_ * L_ * 4)  // 201,326,592 bytes

// ---- scratch (__device__ arrays: no cudaMalloc allowed) ----
__device__ float g_P[(size_t)B_ * L_ * 256];    // P = inp @ W^T (16.7 MB)
__device__ float g_coef[(size_t)B_ * L_ * 8];   // per-layer (a0,a1) x3 (+pad)
__device__ float g_w[(size_t)B_ * L_ * 8];      // 8 effective lookback weights

__device__ __forceinline__ unsigned f2tf32(float x) {
    unsigned u;
    asm("cvt.rna.tf32.f32 %0, %1;" : "=r"(u) : "f"(x));
    return u;
}

__device__ __forceinline__ void mma_tf32(float* c, const unsigned* a, const unsigned* b) {
    asm volatile(
        "mma.sync.aligned.m16n8k8.row.col.f32.tf32.tf32.f32 "
        "{%0,%1,%2,%3}, {%4,%5,%6,%7}, {%8,%9}, {%0,%1,%2,%3};"
        : "+f"(c[0]), "+f"(c[1]), "+f"(c[2]), "+f"(c[3])
        : "r"(a[0]), "r"(a[1]), "r"(a[2]), "r"(a[3]), "r"(b[0]), "r"(b[1]));
}

// =====================================================================
// attention-chain helpers (proven numerics — do not alter)
// =====================================================================
__device__ __forceinline__ void load_row8(float* x, const float* base, int r, int c)
{
    if (r >= 0) {
        float4 v0 = *(const float4*)(base + (size_t)r * D_ + c);
        float4 v1 = *(const float4*)(base + (size_t)r * D_ + c + 4);
        x[0]=v0.x; x[1]=v0.y; x[2]=v0.z; x[3]=v0.w;
        x[4]=v1.x; x[5]=v1.y; x[6]=v1.z; x[7]=v1.w;
    } else {
        #pragma unroll
        for (int k = 0; k < 8; k++) x[k] = 0.f;
    }
}

__device__ __forceinline__ void dot2(const float* u, const float* v, float& p0, float& p1)
{
    float s0 = 0.f, s1 = 0.f;
    #pragma unroll
    for (int k = 0; k < 8; k++) {
        s0 = fmaf(u[k], u[k], s0);
        s1 = fmaf(u[k], v[k], s1);
    }
    #pragma unroll
    for (int o = 16; o; o >>= 1) {
        s0 += __shfl_xor_sync(0xffffffffu, s0, o);
        s1 += __shfl_xor_sync(0xffffffffu, s1, o);
    }
    p0 = s0; p1 = s1;
}

__device__ __forceinline__ void coef2(float p0, float p1, bool valid, float& a0, float& a1)
{
    if (valid) {
        float s0 = p0 * 0.0625f;   // 1/sqrt(256)
        float s1 = p1 * 0.0625f;
        float m  = fmaxf(s0, s1);
        float e0 = expf(s0 - m);
        float e1 = expf(s1 - m);
        float inv = 1.f / (e0 + e1);
        a0 = e0 * inv;
        a1 = e1 * inv;
    } else {
        a0 = 1.f; a1 = 0.f;
    }
}

// =====================================================================
// Kernel 1 (s4): coef + w producer. One warp per (b,l): full chain ->
// per-layer attn coefs (6 floats) + 8 lookback weights.
// =====================================================================
__global__ void __launch_bounds__(256)
coef_kernel(const float* __restrict__ inp)
{
    const int lane = threadIdx.x & 31;
    const int row  = blockIdx.x * 8 + (threadIdx.x >> 5);   // 0..16383
    const int b    = row >> 10;
    const int l    = row & (L_ - 1);
    const float* base = inp + (size_t)b * L_ * D_;
    const int c = lane * 8;

    float al0[4], al1[4];
    float g0, d0, g1, d1;

    float o1[4][8];
    #pragma unroll
    for (int t = 0; t < 4; t++) {
        int lh = l - 2 * t;
        float xh[8], xl[8];
        load_row8(xh, base, lh, c);
        load_row8(xl, base, lh - 1, c);
        float p0, p1; dot2(xh, xl, p0, p1);
        float b0, b1; coef2(p0, p1, lh >= 1, b0, b1);
        al0[t] = b0; al1[t] = b1;
        #pragma unroll
        for (int k = 0; k < 8; k++)
            o1[t][k] = fmaf(b0, xh[k], fmaf(b1, xl[k], xh[k]));
    }
    float o2[2][8];
    #pragma unroll
    for (int t = 0; t < 2; t++) {
        int lh = l - 4 * t;
        float p0, p1; dot2(o1[2 * t], o1[2 * t + 1], p0, p1);
        float b0, b1; coef2(p0, p1, lh >= 2, b0, b1);
        if (t == 0) { g0 = b0; d0 = b1; }
        else        { g1 = b0; d1 = b1; }
        #pragma unroll
        for (int k = 0; k < 8; k++)
            o2[t][k] = fmaf(b0, o1[2 * t][k], fmaf(b1, o1[2 * t + 1][k], o1[2 * t][k]));
    }
    float e0, z0;
    {
        float p0, p1; dot2(o2[0], o2[1], p0, p1);
        coef2(p0, p1, l >= 4, e0, z0);
    }

    if (lane == 0) {
        // per-layer attn coefficients for the scatter
        float* cp = g_coef + (size_t)row * 8;
        *(float4*)(cp)     = make_float4(al0[0], al1[0], g0, d0);
        *(float4*)(cp + 4) = make_float4(e0, z0, 0.f, 0.f);

        // effective lookback weights for the combine
        float eps = 1.f + e0, zet = z0;
        float G0 = 1.f + g0, D0v = d0, G1 = 1.f + g1, D1v = d1;
        float* wp = g_w + (size_t)row * 8;
        *(float4*)(wp)     = make_float4(eps * G0  * (1.f + al0[0]),
                                         eps * G0  * al1[0],
                                         eps * D0v * (1.f + al0[1]),
                                         eps * D0v * al1[1]);
        *(float4*)(wp + 4) = make_float4(zet * G1  * (1.f + al0[2]),
                                         zet * G1  * al1[2],
                                         zet * D1v * (1.f + al0[3]),
                                         zet * D1v * al1[3]);
    }
}

// =====================================================================
// Kernel 2 (s4, after memset+coef): scatter the 2 nonzeros per attn row.
// One thread per row (idx == global attn row index).
// =====================================================================
__global__ void __launch_bounds__(256)
scatter_kernel(float* __restrict__ attn_out)
{
    const int idx   = blockIdx.x * 256 + threadIdx.x;   // 0..49151
    const int b     = idx / (NL_ * L_);
    const int rem   = idx - b * (NL_ * L_);
    const int layer = rem >> 10;
    const int l     = rem & (L_ - 1);
    const int d     = 1 << layer;

    const float* cp = g_coef + ((size_t)(b * L_ + l)) * 8 + layer * 2;
    const float a0 = cp[0];
    const float a1 = cp[1];

    float* rowp = attn_out + (size_t)idx * L_;
    rowp[l] = a0;
    if (l >= d) rowp[l - d] = a1;
}

// =====================================================================
// Kernel 3 (s3): P = inp @ W^T over all 16384 rows. (proven, 22.3us)
// =====================================================================
#define GBM 128
#define GBN 128
#define GBK 32
#define SST 36

__global__ void __launch_bounds__(256, 2)
gemmP_kernel(const float* __restrict__ inp, const float* __restrict__ W)
{
    __shared__ unsigned As[GBM * SST];
    __shared__ unsigned Bs[GBN * SST];

    const int tid  = threadIdx.x;
    const int m0   = blockIdx.x * GBM;
    const int n0   = blockIdx.y * GBN;
    const int wid  = tid >> 5;
    const int lane = tid & 31;
    const int warp_m = wid & 3;
    const int warp_n = wid >> 2;
    const int gid = lane >> 2;
    const int tig = lane & 3;

    float acc[2][8][4];
    #pragma unroll
    for (int i = 0; i < 2; i++)
        #pragma unroll
        for (int j = 0; j < 8; j++)
            #pragma unroll
            for (int k = 0; k < 4; k++) acc[i][j][k] = 0.f;

    const float* aPtr[4];
    const float* bPtr[4];
    int sOff[4];
    #pragma unroll
    for (int it = 0; it < 4; it++) {
        int idx = tid + it * 256;
        int r   = idx >> 3;
        int q   = idx & 7;
        aPtr[it] = inp + (size_t)(m0 + r) * 256 + q * 4;
        bPtr[it] = W + (size_t)(n0 + r) * 256 + q * 4;
        sOff[it] = r * SST + q * 4;
    }

    float4 aR[4], bR[4];
    #pragma unroll
    for (int it = 0; it < 4; it++) {
        aR[it] = *(const float4*)(aPtr[it]);
        bR[it] = *(const float4*)(bPtr[it]);
    }

    #pragma unroll
    for (int i = 0; i < 8; i++) {
        const int kc = i * GBK;
        __syncthreads();
        #pragma unroll
        for (int it = 0; it < 4; it++) {
            *(uint4*)(As + sOff[it]) =
                make_uint4(f2tf32(aR[it].x), f2tf32(aR[it].y), f2tf32(aR[it].z), f2tf32(aR[it].w));
            *(uint4*)(Bs + sOff[it]) =
                make_uint4(f2tf32(bR[it].x), f2tf32(bR[it].y), f2tf32(bR[it].z), f2tf32(bR[it].w));
        }
        __syncthreads();

        if (i < 7) {
            #pragma unroll
            for (int it = 0; it < 4; it++) {
                aR[it] = *(const float4*)(aPtr[it] + kc + GBK);
                bR[it] = *(const float4*)(bPtr[it] + kc + GBK);
            }
        }

        #pragma unroll
        for (int kk = 0; kk < GBK; kk += 8) {
            unsigned a[2][4], bq[8][2];
            #pragma unroll
            for (int mt = 0; mt < 2; mt++) {
                int r = warp_m * 32 + mt * 16 + gid;
                a[mt][0] = As[r * SST + kk + tig];
                a[mt][1] = As[(r + 8) * SST + kk + tig];
                a[mt][2] = As[r * SST + kk + tig + 4];
                a[mt][3] = As[(r + 8) * SST + kk + tig + 4];
            }
            #pragma unroll
            for (int nt = 0; nt < 8; nt++) {
                int cix = warp_n * 64 + nt * 8 + gid;
                bq[nt][0] = Bs[cix * SST + kk + tig];
                bq[nt][1] = Bs[cix * SST + kk + tig + 4];
            }
            #pragma unroll
            for (int mt = 0; mt < 2; mt++)
                #pragma unroll
                for (int nt = 0; nt < 8; nt++)
                    mma_tf32(acc[mt][nt], a[mt], bq[nt]);
        }
    }

    #pragma unroll
    for (int mt = 0; mt < 2; mt++) {
        #pragma unroll
        for (int half = 0; half < 2; half++) {
            int m = m0 + warp_m * 32 + mt * 16 + gid + half * 8;
            float* prow = g_P + (size_t)m * 256;
            #pragma unroll
            for (int nt = 0; nt < 8; nt++) {
                int col = n0 + warp_n * 64 + nt * 8 + 2 * tig;
                *(float2*)(prow + col) =
                    make_float2(acc[mt][nt][half * 2 + 0], acc[mt][nt][half * 2 + 1]);
            }
        }
    }
}

// =====================================================================
// Kernel 4 (s3, after gemmP + coef): o = sum_j w_j * P[l-j] + bias + res
// (round-9 proven, 11.2us)
// =====================================================================
#define RPT 4

__global__ void __launch_bounds__(256)
combine_kernel(const float* __restrict__ inp, const float* __restrict__ bias,
               float* __restrict__ o_out)
{
    const int tid  = threadIdx.x;
    const int grp  = blockIdx.x * 4 + (tid >> 6);
    const int colq = tid & 63;
    const int col  = colq * 4;

    const int mb   = grp * RPT;
    const int b    = mb / LQ_;
    const int lq0  = mb - b * LQ_;
    const int l0   = lq0 + PAST_;

    const float4 bi = *(const float4*)(bias + col);
    const float* pbase = g_P + ((size_t)b * L_) * 256 + col;
    const float* wbase = g_w + ((size_t)b * L_ + l0) * 8;
    const float* rbase = inp + ((size_t)b * L_ + l0) * D_ + (col & 63);
    float* obase = o_out + (size_t)mb * 256 + col;

    float4 p[8];
    #pragma unroll
    for (int i = 0; i < 8; i++)
        p[i] = *(const float4*)(pbase + (size_t)(l0 - 7 + i) * 256);

    #pragma unroll
    for (int r = 0; r < RPT; r++) {
        const float4 w0 = *(const float4*)(wbase + r * 8);
        const float4 w1 = *(const float4*)(wbase + r * 8 + 4);
        const float4 rv = *(const float4*)(rbase + (size_t)r * D_);

        float4 acc;
        acc.x = bi.x + rv.x; acc.y = bi.y + rv.y;
        acc.z = bi.z + rv.z; acc.w = bi.w + rv.w;
        const float wj[8] = { w0.x, w0.y, w0.z, w0.w, w1.x, w1.y, w1.z, w1.w };
        #pragma unroll
        for (int j = 0; j < 8; j++) {
            const float4 pv = p[7 - j];
            acc.x = fmaf(wj[j], pv.x, acc.x);
            acc.y = fmaf(wj[j], pv.y, acc.y);
            acc.z = fmaf(wj[j], pv.z, acc.z);
            acc.w = fmaf(wj[j], pv.w, acc.w);
        }
        __stcs((float4*)(obase + (size_t)r * 256), acc);

        if (r < RPT - 1) {
            #pragma unroll
            for (int i = 0; i < 7; i++) p[i] = p[i + 1];
            p[7] = *(const float4*)(pbase + (size_t)(l0 + r + 1) * 256);
        }
    }
}

// =====================================================================
// launch DAG:
//   s2: memset(attn)                        (DRAM-write engine)
//   s3: gemmP -> [wait coef] combine        (tensor/L2)
//   s4: coef  -> [wait memset] scatter      (ALU/L2-read)
// =====================================================================
static cudaStream_t g_s2 = 0, g_s3 = 0, g_s4 = 0;
static cudaEvent_t  g_fork = 0, g_mset = 0, g_coefE = 0, g_j2 = 0, g_j3 = 0, g_j4 = 0;
static struct StreamInit {
    StreamInit() {
        cudaStreamCreateWithFlags(&g_s2, cudaStreamNonBlocking);
        cudaStreamCreateWithFlags(&g_s3, cudaStreamNonBlocking);
        cudaStreamCreateWithFlags(&g_s4, cudaStreamNonBlocking);
        cudaEventCreateWithFlags(&g_fork,  cudaEventDisableTiming);
        cudaEventCreateWithFlags(&g_mset,  cudaEventDisableTiming);
        cudaEventCreateWithFlags(&g_coefE, cudaEventDisableTiming);
        cudaEventCreateWithFlags(&g_j2, cudaEventDisableTiming);
        cudaEventCreateWithFlags(&g_j3, cudaEventDisableTiming);
        cudaEventCreateWithFlags(&g_j4, cudaEventDisableTiming);
    }
} g_stream_init;

extern "C" void kernel_launch(void* const* d_in, const int* in_sizes, int n_in,
                              void* d_out, int out_size)
{
    const float* inp  = (const float*)d_in[0];
    const float* W    = (const float*)d_in[1];
    const float* bias = (const float*)d_in[2];
    // d_in[3] = masks : compile-time structure, unused

    float* out  = (float*)d_out;           // o : (16, 1008, 4, 64)
    float* attn = out + O_ELEMS;           // attn_stack : (16, 3, 1024, 1024)

    cudaEventRecord(g_fork, 0);
    cudaStreamWaitEvent(g_s2, g_fork, 0);
    cudaStreamWaitEvent(g_s3, g_fork, 0);
    cudaStreamWaitEvent(g_s4, g_fork, 0);

    // s2: zero the whole attn_stack at memset bandwidth
    cudaMemsetAsync(attn, 0, ATTN_BYTES, g_s2);
    cudaEventRecord(g_mset, g_s2);

    // s4: coefficient chains
    coef_kernel<<<(B_ * L_) / 8, 256, 0, g_s4>>>(inp);
    cudaEventRecord(g_coefE, g_s4);

    // s3: gemm
    gemmP_kernel<<<dim3((B_ * L_) / GBM, 256 / GBN), 256, 0, g_s3>>>(inp, W);

    // s3: combine (needs P in-order + coef via event)
    cudaStreamWaitEvent(g_s3, g_coefE, 0);
    combine_kernel<<<(B_ * LQ_ / RPT) / 4, 256, 0, g_s3>>>(inp, bias, out);

    // s4: scatter (needs coef in-order + memset via event)
    cudaStreamWaitEvent(g_s4, g_mset, 0);
    scatter_kernel<<<(B_ * NL_ * L_) / 256, 256, 0, g_s4>>>(attn);

    // join
    cudaEventRecord(g_j2, g_s2);
    cudaEventRecord(g_j3, g_s3);
    cudaEventRecord(g_j4, g_s4);
    cudaStreamWaitEvent(0, g_j2, 0);
    cudaStreamWaitEvent(0, g_j3, 0);
    cudaStreamWaitEvent(0, g_j4, 0);
}

// round 16
// speedup vs baseline: 1.1893x; 1.1893x over previous
#include <cuda_runtime.h>
#include <cstdint>

// Problem constants
#define B_     16
#define L_     1024
#define D_     256
#define PAST_  16
#define LQ_    (L_ - PAST_)   // 1008
#define NL_    3

#define O_ELEMS   ((size_t)B_ * LQ_ * 256)   // 4,128,768 floats

// ---- scratch (__device__ arrays: no cudaMalloc allowed) ----
__device__ float g_P[(size_t)B_ * L_ * 256];   // P = inp @ W^T over ALL rows (16.7 MB)
__device__ float g_w[(size_t)B_ * L_ * 8];     // 8 effective lookback weights per (b,l)

__device__ __forceinline__ unsigned f2tf32(float x) {
    unsigned u;
    asm("cvt.rna.tf32.f32 %0, %1;" : "=r"(u) : "f"(x));
    return u;
}

__device__ __forceinline__ void mma_tf32(float* c, const unsigned* a, const unsigned* b) {
    asm volatile(
        "mma.sync.aligned.m16n8k8.row.col.f32.tf32.tf32.f32 "
        "{%0,%1,%2,%3}, {%4,%5,%6,%7}, {%8,%9}, {%0,%1,%2,%3};"
        : "+f"(c[0]), "+f"(c[1]), "+f"(c[2]), "+f"(c[3])
        : "r"(a[0]), "r"(a[1]), "r"(a[2]), "r"(a[3]), "r"(b[0]), "r"(b[1]));
}

// =====================================================================
// attention-chain helpers (proven numerics — do not alter)
// =====================================================================
__device__ __forceinline__ void load_row8(float* x, const float* base, int r, int c)
{
    if (r >= 0) {
        float4 v0 = *(const float4*)(base + (size_t)r * D_ + c);
        float4 v1 = *(const float4*)(base + (size_t)r * D_ + c + 4);
        x[0]=v0.x; x[1]=v0.y; x[2]=v0.z; x[3]=v0.w;
        x[4]=v1.x; x[5]=v1.y; x[6]=v1.z; x[7]=v1.w;
    } else {
        #pragma unroll
        for (int k = 0; k < 8; k++) x[k] = 0.f;
    }
}

__device__ __forceinline__ void dot2(const float* u, const float* v, float& p0, float& p1)
{
    float s0 = 0.f, s1 = 0.f;
    #pragma unroll
    for (int k = 0; k < 8; k++) {
        s0 = fmaf(u[k], u[k], s0);
        s1 = fmaf(u[k], v[k], s1);
    }
    #pragma unroll
    for (int o = 16; o; o >>= 1) {
        s0 += __shfl_xor_sync(0xffffffffu, s0, o);
        s1 += __shfl_xor_sync(0xffffffffu, s1, o);
    }
    p0 = s0; p1 = s1;
}

__device__ __forceinline__ void coef2(float p0, float p1, bool valid, float& a0, float& a1)
{
    if (valid) {
        float s0 = p0 * 0.0625f;   // 1/sqrt(256)
        float s1 = p1 * 0.0625f;
        float m  = fmaxf(s0, s1);
        float e0 = expf(s0 - m);
        float e1 = expf(s1 - m);
        float inv = 1.f / (e0 + e1);
        a0 = e0 * inv;
        a1 = e1 * inv;
    } else {
        a0 = 1.f; a1 = 0.f;
    }
}

// =====================================================================
// Kernel A (s2, recorded first): attn fill + w weights.
// One warp per (b,l). (round-12 proven, 39.6us)
// =====================================================================
__global__ void __launch_bounds__(256)
fill_kernel(const float* __restrict__ inp, float* __restrict__ attn_out)
{
    const int lane = threadIdx.x & 31;
    const int row  = blockIdx.x * 8 + (threadIdx.x >> 5);   // 0..16383
    const int b    = row >> 10;
    const int l    = row & (L_ - 1);
    const float* base = inp + (size_t)b * L_ * D_;
    const int c = lane * 8;

    float A0[NL_], A1[NL_];
    float al0[4], al1[4];
    float g0, d0, g1, d1;

    float o1[4][8];
    #pragma unroll
    for (int t = 0; t < 4; t++) {
        int lh = l - 2 * t;
        float xh[8], xl[8];
        load_row8(xh, base, lh, c);
        load_row8(xl, base, lh - 1, c);
        float p0, p1; dot2(xh, xl, p0, p1);
        float b0, b1; coef2(p0, p1, lh >= 1, b0, b1);
        al0[t] = b0; al1[t] = b1;
        #pragma unroll
        for (int k = 0; k < 8; k++)
            o1[t][k] = fmaf(b0, xh[k], fmaf(b1, xl[k], xh[k]));
        if (t == 0) { A0[0] = b0; A1[0] = b1; }
    }
    float o2[2][8];
    #pragma unroll
    for (int t = 0; t < 2; t++) {
        int lh = l - 4 * t;
        float p0, p1; dot2(o1[2 * t], o1[2 * t + 1], p0, p1);
        float b0, b1; coef2(p0, p1, lh >= 2, b0, b1);
        if (t == 0) { g0 = b0; d0 = b1; A0[1] = b0; A1[1] = b1; }
        else        { g1 = b0; d1 = b1; }
        #pragma unroll
        for (int k = 0; k < 8; k++)
            o2[t][k] = fmaf(b0, o1[2 * t][k], fmaf(b1, o1[2 * t + 1][k], o1[2 * t][k]));
    }
    float e0, z0;
    {
        float p0, p1; dot2(o2[0], o2[1], p0, p1);
        coef2(p0, p1, l >= 4, e0, z0);
        A0[2] = e0; A1[2] = z0;
    }

    if (lane == 0) {
        float eps = 1.f + e0, zet = z0;
        float G0 = 1.f + g0, D0v = d0, G1 = 1.f + g1, D1v = d1;
        float* wp = g_w + (size_t)row * 8;
        *(float4*)(wp)     = make_float4(eps * G0  * (1.f + al0[0]),
                                         eps * G0  * al1[0],
                                         eps * D0v * (1.f + al0[1]),
                                         eps * D0v * al1[1]);
        *(float4*)(wp + 4) = make_float4(zet * G1  * (1.f + al0[2]),
                                         zet * G1  * al1[2],
                                         zet * D1v * (1.f + al0[3]),
                                         zet * D1v * al1[3]);
    }

    #pragma unroll
    for (int layer = 0; layer < NL_; layer++) {
        const int d  = 1 << layer;
        const int c0 = l;
        const int c1 = l - d;
        const float a0 = A0[layer];
        const float a1 = A1[layer];
        float4* dst = (float4*)(attn_out + ((size_t)(b * NL_ + layer) * L_ + l) * L_);
        #pragma unroll
        for (int s = 0; s < 8; s++) {
            int q = lane + (s << 5);
            float4 v = make_float4(0.f, 0.f, 0.f, 0.f);
            if ((c0 >> 2) == q)              ((float*)&v)[c0 & 3] = a0;
            if (c1 >= 0 && (c1 >> 2) == q)   ((float*)&v)[c1 & 3] = a1;
            __stcs(dst + q, v);
        }
    }
}

// =====================================================================
// Kernel B (s3): P = inp @ W^T over all 16384 rows.
// 64x64 tiles, SAME resource footprint as a fill CTA (64 regs, 18KB smem)
// so it backfills slots as fill CTAs retire. Register prefetch.
// =====================================================================
#define PST 36   // padded smem k-stride

__global__ void __launch_bounds__(256, 4)
gemm64P_kernel(const float* __restrict__ inp, const float* __restrict__ W)
{
    __shared__ unsigned As[64 * PST];
    __shared__ unsigned Bs[64 * PST];

    const int tid  = threadIdx.x;
    const int m0   = blockIdx.x * 64;
    const int n0   = blockIdx.y * 64;
    const int wid  = tid >> 5;
    const int lane = tid & 31;
    const int warp_m = wid & 3;    // 4 warps in M (16 rows each)
    const int warp_n = wid >> 2;   // 2 warps in N (32 cols each)
    const int gid = lane >> 2;
    const int tig = lane & 3;

    const float* aP[2];
    const float* bP[2];
    int sOff[2];
    #pragma unroll
    for (int it = 0; it < 2; it++) {
        int idx = tid + it * 256;    // 512 float4 per matrix per chunk
        int r   = idx >> 3;
        int q   = idx & 7;
        aP[it]  = inp + (size_t)(m0 + r) * 256 + q * 4;
        bP[it]  = W + (size_t)(n0 + r) * 256 + q * 4;
        sOff[it] = r * PST + q * 4;
    }

    float acc[4][4];
    #pragma unroll
    for (int j = 0; j < 4; j++)
        #pragma unroll
        for (int k = 0; k < 4; k++) acc[j][k] = 0.f;

    // preload chunk 0
    float4 aR[2], bR[2];
    #pragma unroll
    for (int it = 0; it < 2; it++) {
        aR[it] = *(const float4*)(aP[it]);
        bR[it] = *(const float4*)(bP[it]);
    }

    #pragma unroll
    for (int i = 0; i < 8; i++) {
        const int kc = i * 32;
        __syncthreads();
        #pragma unroll
        for (int it = 0; it < 2; it++) {
            *(uint4*)(As + sOff[it]) =
                make_uint4(f2tf32(aR[it].x), f2tf32(aR[it].y), f2tf32(aR[it].z), f2tf32(aR[it].w));
            *(uint4*)(Bs + sOff[it]) =
                make_uint4(f2tf32(bR[it].x), f2tf32(bR[it].y), f2tf32(bR[it].z), f2tf32(bR[it].w));
        }
        __syncthreads();

        if (i < 7) {
            #pragma unroll
            for (int it = 0; it < 2; it++) {
                aR[it] = *(const float4*)(aP[it] + kc + 32);
                bR[it] = *(const float4*)(bP[it] + kc + 32);
            }
        }

        #pragma unroll
        for (int kk = 0; kk < 32; kk += 8) {
            unsigned a[4], bq[4][2];
            int r = warp_m * 16 + gid;
            a[0] = As[r * PST + kk + tig];
            a[1] = As[(r + 8) * PST + kk + tig];
            a[2] = As[r * PST + kk + tig + 4];
            a[3] = As[(r + 8) * PST + kk + tig + 4];
            #pragma unroll
            for (int nt = 0; nt < 4; nt++) {
                int cix = warp_n * 32 + nt * 8 + gid;
                bq[nt][0] = Bs[cix * PST + kk + tig];
                bq[nt][1] = Bs[cix * PST + kk + tig + 4];
            }
            #pragma unroll
            for (int nt = 0; nt < 4; nt++)
                mma_tf32(acc[nt], a, bq[nt]);
        }
    }

    // write P tile
    #pragma unroll
    for (int half = 0; half < 2; half++) {
        int m = m0 + warp_m * 16 + gid + half * 8;
        float* prow = g_P + (size_t)m * 256;
        #pragma unroll
        for (int nt = 0; nt < 4; nt++) {
            int col = n0 + warp_n * 32 + nt * 8 + 2 * tig;
            *(float2*)(prow + col) =
                make_float2(acc[nt][half * 2 + 0], acc[nt][half * 2 + 1]);
        }
    }
}

// =====================================================================
// Kernel C (join): o[b,l] = sum_j w_j(l) * P[b,l-j] + bias + residual
// (round-9 proven, 11.2us)
// =====================================================================
#define RPT 4

__global__ void __launch_bounds__(256)
combine_kernel(const float* __restrict__ inp, const float* __restrict__ bias,
               float* __restrict__ o_out)
{
    const int tid  = threadIdx.x;
    const int grp  = blockIdx.x * 4 + (tid >> 6);
    const int colq = tid & 63;
    const int col  = colq * 4;

    const int mb   = grp * RPT;
    const int b    = mb / LQ_;
    const int lq0  = mb - b * LQ_;
    const int l0   = lq0 + PAST_;

    const float4 bi = *(const float4*)(bias + col);
    const float* pbase = g_P + ((size_t)b * L_) * 256 + col;
    const float* wbase = g_w + ((size_t)b * L_ + l0) * 8;
    const float* rbase = inp + ((size_t)b * L_ + l0) * D_ + (col & 63);
    float* obase = o_out + (size_t)mb * 256 + col;

    float4 p[8];
    #pragma unroll
    for (int i = 0; i < 8; i++)
        p[i] = *(const float4*)(pbase + (size_t)(l0 - 7 + i) * 256);

    #pragma unroll
    for (int r = 0; r < RPT; r++) {
        const float4 w0 = *(const float4*)(wbase + r * 8);
        const float4 w1 = *(const float4*)(wbase + r * 8 + 4);
        const float4 rv = *(const float4*)(rbase + (size_t)r * D_);

        float4 acc;
        acc.x = bi.x + rv.x; acc.y = bi.y + rv.y;
        acc.z = bi.z + rv.z; acc.w = bi.w + rv.w;
        const float wj[8] = { w0.x, w0.y, w0.z, w0.w, w1.x, w1.y, w1.z, w1.w };
        #pragma unroll
        for (int j = 0; j < 8; j++) {
            const float4 pv = p[7 - j];
            acc.x = fmaf(wj[j], pv.x, acc.x);
            acc.y = fmaf(wj[j], pv.y, acc.y);
            acc.z = fmaf(wj[j], pv.z, acc.z);
            acc.w = fmaf(wj[j], pv.w, acc.w);
        }
        __stcs((float4*)(obase + (size_t)r * 256), acc);

        if (r < RPT - 1) {
            #pragma unroll
            for (int i = 0; i < 7; i++) p[i] = p[i + 1];
            p[7] = *(const float4*)(pbase + (size_t)(l0 + r + 1) * 256);
        }
    }
}

// =====================================================================
// launch: round-12 DAG (proven best): fill recorded FIRST on s2,
// gemm on s3 backfills, combine after both. No priorities.
// =====================================================================
static cudaStream_t g_s2 = 0, g_s3 = 0;
static cudaEvent_t  g_fork = 0, g_j2 = 0, g_j3 = 0;
static struct StreamInit {
    StreamInit() {
        cudaStreamCreateWithFlags(&g_s2, cudaStreamNonBlocking);
        cudaStreamCreateWithFlags(&g_s3, cudaStreamNonBlocking);
        cudaEventCreateWithFlags(&g_fork, cudaEventDisableTiming);
        cudaEventCreateWithFlags(&g_j2, cudaEventDisableTiming);
        cudaEventCreateWithFlags(&g_j3, cudaEventDisableTiming);
    }
} g_stream_init;

extern "C" void kernel_launch(void* const* d_in, const int* in_sizes, int n_in,
                              void* d_out, int out_size)
{
    const float* inp  = (const float*)d_in[0];
    const float* W    = (const float*)d_in[1];
    const float* bias = (const float*)d_in[2];
    // d_in[3] = masks : compile-time structure, unused

    float* out  = (float*)d_out;           // o : (16, 1008, 4, 64)
    float* attn = out + O_ELEMS;           // attn_stack : (16, 3, 1024, 1024)

    cudaEventRecord(g_fork, 0);
    cudaStreamWaitEvent(g_s2, g_fork, 0);
    cudaStreamWaitEvent(g_s3, g_fork, 0);

    fill_kernel<<<(B_ * L_) / 8, 256, 0, g_s2>>>(inp, attn);
    gemm64P_kernel<<<dim3((B_ * L_) / 64, 4), 256, 0, g_s3>>>(inp, W);

    cudaEventRecord(g_j2, g_s2);
    cudaEventRecord(g_j3, g_s3);
    cudaStreamWaitEvent(0, g_j2, 0);
    cudaStreamWaitEvent(0, g_j3, 0);

    combine_kernel<<<(B_ * LQ_ / RPT) / 4, 256>>>(inp, bias, out);
}

// round 17
// speedup vs baseline: 1.3297x; 1.1180x over previous
#include <cuda_runtime.h>
#include <cstdint>

// Problem constants
#define B_     16
#define L_     1024
#define D_     256
#define PAST_  16
#define LQ_    (L_ - PAST_)   // 1008
#define NL_    3

#define O_ELEMS   ((size_t)B_ * LQ_ * 256)   // 4,128,768 floats

// ---- scratch (__device__ arrays: no cudaMalloc allowed) ----
__device__ float g_P[(size_t)B_ * L_ * 256];   // P = inp @ W^T over ALL rows (16.7 MB)
__device__ float g_w[(size_t)B_ * L_ * 8];     // 8 effective lookback weights per (b,l)

__device__ __forceinline__ unsigned f2tf32(float x) {
    unsigned u;
    asm("cvt.rna.tf32.f32 %0, %1;" : "=r"(u) : "f"(x));
    return u;
}

__device__ __forceinline__ void mma_tf32(float* c, const unsigned* a, const unsigned* b) {
    asm volatile(
        "mma.sync.aligned.m16n8k8.row.col.f32.tf32.tf32.f32 "
        "{%0,%1,%2,%3}, {%4,%5,%6,%7}, {%8,%9}, {%0,%1,%2,%3};"
        : "+f"(c[0]), "+f"(c[1]), "+f"(c[2]), "+f"(c[3])
        : "r"(a[0]), "r"(a[1]), "r"(a[2]), "r"(a[3]), "r"(b[0]), "r"(b[1]));
}

// =====================================================================
// attention-chain helpers (proven numerics — do not alter)
// =====================================================================
__device__ __forceinline__ void load_row8(float* x, const float* base, int r, int c)
{
    if (r >= 0) {
        float4 v0 = *(const float4*)(base + (size_t)r * D_ + c);
        float4 v1 = *(const float4*)(base + (size_t)r * D_ + c + 4);
        x[0]=v0.x; x[1]=v0.y; x[2]=v0.z; x[3]=v0.w;
        x[4]=v1.x; x[5]=v1.y; x[6]=v1.z; x[7]=v1.w;
    } else {
        #pragma unroll
        for (int k = 0; k < 8; k++) x[k] = 0.f;
    }
}

__device__ __forceinline__ void dot2(const float* u, const float* v, float& p0, float& p1)
{
    float s0 = 0.f, s1 = 0.f;
    #pragma unroll
    for (int k = 0; k < 8; k++) {
        s0 = fmaf(u[k], u[k], s0);
        s1 = fmaf(u[k], v[k], s1);
    }
    #pragma unroll
    for (int o = 16; o; o >>= 1) {
        s0 += __shfl_xor_sync(0xffffffffu, s0, o);
        s1 += __shfl_xor_sync(0xffffffffu, s1, o);
    }
    p0 = s0; p1 = s1;
}

__device__ __forceinline__ void coef2(float p0, float p1, bool valid, float& a0, float& a1)
{
    if (valid) {
        float s0 = p0 * 0.0625f;   // 1/sqrt(256)
        float s1 = p1 * 0.0625f;
        float m  = fmaxf(s0, s1);
        float e0 = expf(s0 - m);
        float e1 = expf(s1 - m);
        float inv = 1.f / (e0 + e1);
        a0 = e0 * inv;
        a1 = e1 * inv;
    } else {
        a0 = 1.f; a1 = 0.f;
    }
}

// =====================================================================
// Kernel A (s2, recorded first): attn fill + w weights.
// One warp per (b,l). Store section: unconditional zero STG.128 stream,
// then owning-lane scalar patches (same-thread ordering, no sync).
// =====================================================================
__global__ void __launch_bounds__(256)
fill_kernel(const float* __restrict__ inp, float* __restrict__ attn_out)
{
    const int lane = threadIdx.x & 31;
    const int row  = blockIdx.x * 8 + (threadIdx.x >> 5);   // 0..16383
    const int b    = row >> 10;
    const int l    = row & (L_ - 1);
    const float* base = inp + (size_t)b * L_ * D_;
    const int c = lane * 8;

    float A0[NL_], A1[NL_];
    float al0[4], al1[4];
    float g0, d0, g1, d1;

    float o1[4][8];
    #pragma unroll
    for (int t = 0; t < 4; t++) {
        int lh = l - 2 * t;
        float xh[8], xl[8];
        load_row8(xh, base, lh, c);
        load_row8(xl, base, lh - 1, c);
        float p0, p1; dot2(xh, xl, p0, p1);
        float b0, b1; coef2(p0, p1, lh >= 1, b0, b1);
        al0[t] = b0; al1[t] = b1;
        #pragma unroll
        for (int k = 0; k < 8; k++)
            o1[t][k] = fmaf(b0, xh[k], fmaf(b1, xl[k], xh[k]));
        if (t == 0) { A0[0] = b0; A1[0] = b1; }
    }
    float o2[2][8];
    #pragma unroll
    for (int t = 0; t < 2; t++) {
        int lh = l - 4 * t;
        float p0, p1; dot2(o1[2 * t], o1[2 * t + 1], p0, p1);
        float b0, b1; coef2(p0, p1, lh >= 2, b0, b1);
        if (t == 0) { g0 = b0; d0 = b1; A0[1] = b0; A1[1] = b1; }
        else        { g1 = b0; d1 = b1; }
        #pragma unroll
        for (int k = 0; k < 8; k++)
            o2[t][k] = fmaf(b0, o1[2 * t][k], fmaf(b1, o1[2 * t + 1][k], o1[2 * t][k]));
    }
    float e0, z0;
    {
        float p0, p1; dot2(o2[0], o2[1], p0, p1);
        coef2(p0, p1, l >= 4, e0, z0);
        A0[2] = e0; A1[2] = z0;
    }

    if (lane == 0) {
        float eps = 1.f + e0, zet = z0;
        float G0 = 1.f + g0, D0v = d0, G1 = 1.f + g1, D1v = d1;
        float* wp = g_w + (size_t)row * 8;
        *(float4*)(wp)     = make_float4(eps * G0  * (1.f + al0[0]),
                                         eps * G0  * al1[0],
                                         eps * D0v * (1.f + al0[1]),
                                         eps * D0v * al1[1]);
        *(float4*)(wp + 4) = make_float4(zet * G1  * (1.f + al0[2]),
                                         zet * G1  * al1[2],
                                         zet * D1v * (1.f + al0[3]),
                                         zet * D1v * al1[3]);
    }

    // ---- store 3 attn rows: pure-zero STG.128 stream + owning-lane patch ----
    const float4 z4 = make_float4(0.f, 0.f, 0.f, 0.f);
    const int lane_c0 = (l >> 2) & 31;     // lane whose float4 covers column l
    #pragma unroll
    for (int layer = 0; layer < NL_; layer++) {
        const int d  = 1 << layer;
        const int c1 = l - d;
        float* rowp = attn_out + ((size_t)(b * NL_ + layer) * L_ + l) * L_;
        float4* dst = (float4*)rowp;

        #pragma unroll
        for (int s = 0; s < 8; s++)
            __stcs(dst + (lane + (s << 5)), z4);

        // patches: same thread that wrote the covering zero-float4 ->
        // program order guarantees the patch lands after the zero.
        if (lane == lane_c0)
            rowp[l] = A0[layer];
        if (c1 >= 0 && lane == ((c1 >> 2) & 31))
            rowp[c1] = A1[layer];
    }
}

// =====================================================================
// Kernel B (s3): P = inp @ W^T over all 16384 rows.
// (round-12 proven gemm128, 22.3us solo)
// =====================================================================
#define GBM 128
#define GBN 128
#define GBK 32
#define SST 36

__global__ void __launch_bounds__(256, 2)
gemmP_kernel(const float* __restrict__ inp, const float* __restrict__ W)
{
    __shared__ unsigned As[GBM * SST];
    __shared__ unsigned Bs[GBN * SST];

    const int tid  = threadIdx.x;
    const int m0   = blockIdx.x * GBM;
    const int n0   = blockIdx.y * GBN;
    const int wid  = tid >> 5;
    const int lane = tid & 31;
    const int warp_m = wid & 3;
    const int warp_n = wid >> 2;
    const int gid = lane >> 2;
    const int tig = lane & 3;

    float acc[2][8][4];
    #pragma unroll
    for (int i = 0; i < 2; i++)
        #pragma unroll
        for (int j = 0; j < 8; j++)
            #pragma unroll
            for (int k = 0; k < 4; k++) acc[i][j][k] = 0.f;

    const float* aPtr[4];
    const float* bPtr[4];
    int sOff[4];
    #pragma unroll
    for (int it = 0; it < 4; it++) {
        int idx = tid + it * 256;
        int r   = idx >> 3;
        int q   = idx & 7;
        aPtr[it] = inp + (size_t)(m0 + r) * 256 + q * 4;
        bPtr[it] = W + (size_t)(n0 + r) * 256 + q * 4;
        sOff[it] = r * SST + q * 4;
    }

    float4 aR[4], bR[4];
    #pragma unroll
    for (int it = 0; it < 4; it++) {
        aR[it] = *(const float4*)(aPtr[it]);
        bR[it] = *(const float4*)(bPtr[it]);
    }

    #pragma unroll
    for (int i = 0; i < 8; i++) {
        const int kc = i * GBK;
        __syncthreads();
        #pragma unroll
        for (int it = 0; it < 4; it++) {
            *(uint4*)(As + sOff[it]) =
                make_uint4(f2tf32(aR[it].x), f2tf32(aR[it].y), f2tf32(aR[it].z), f2tf32(aR[it].w));
            *(uint4*)(Bs + sOff[it]) =
                make_uint4(f2tf32(bR[it].x), f2tf32(bR[it].y), f2tf32(bR[it].z), f2tf32(bR[it].w));
        }
        __syncthreads();

        if (i < 7) {
            #pragma unroll
            for (int it = 0; it < 4; it++) {
                aR[it] = *(const float4*)(aPtr[it] + kc + GBK);
                bR[it] = *(const float4*)(bPtr[it] + kc + GBK);
            }
        }

        #pragma unroll
        for (int kk = 0; kk < GBK; kk += 8) {
            unsigned a[2][4], bq[8][2];
            #pragma unroll
            for (int mt = 0; mt < 2; mt++) {
                int r = warp_m * 32 + mt * 16 + gid;
                a[mt][0] = As[r * SST + kk + tig];
                a[mt][1] = As[(r + 8) * SST + kk + tig];
                a[mt][2] = As[r * SST + kk + tig + 4];
                a[mt][3] = As[(r + 8) * SST + kk + tig + 4];
            }
            #pragma unroll
            for (int nt = 0; nt < 8; nt++) {
                int cix = warp_n * 64 + nt * 8 + gid;
                bq[nt][0] = Bs[cix * SST + kk + tig];
                bq[nt][1] = Bs[cix * SST + kk + tig + 4];
            }
            #pragma unroll
            for (int mt = 0; mt < 2; mt++)
                #pragma unroll
                for (int nt = 0; nt < 8; nt++)
                    mma_tf32(acc[mt][nt], a[mt], bq[nt]);
        }
    }

    #pragma unroll
    for (int mt = 0; mt < 2; mt++) {
        #pragma unroll
        for (int half = 0; half < 2; half++) {
            int m = m0 + warp_m * 32 + mt * 16 + gid + half * 8;
            float* prow = g_P + (size_t)m * 256;
            #pragma unroll
            for (int nt = 0; nt < 8; nt++) {
                int col = n0 + warp_n * 64 + nt * 8 + 2 * tig;
                *(float2*)(prow + col) =
                    make_float2(acc[mt][nt][half * 2 + 0], acc[mt][nt][half * 2 + 1]);
            }
        }
    }
}

// =====================================================================
// Kernel C (join): o[b,l] = sum_j w_j(l) * P[b,l-j] + bias + residual
// (round-9 proven, 11.2us)
// =====================================================================
#define RPT 4

__global__ void __launch_bounds__(256)
combine_kernel(const float* __restrict__ inp, const float* __restrict__ bias,
               float* __restrict__ o_out)
{
    const int tid  = threadIdx.x;
    const int grp  = blockIdx.x * 4 + (tid >> 6);
    const int colq = tid & 63;
    const int col  = colq * 4;

    const int mb   = grp * RPT;
    const int b    = mb / LQ_;
    const int lq0  = mb - b * LQ_;
    const int l0   = lq0 + PAST_;

    const float4 bi = *(const float4*)(bias + col);
    const float* pbase = g_P + ((size_t)b * L_) * 256 + col;
    const float* wbase = g_w + ((size_t)b * L_ + l0) * 8;
    const float* rbase = inp + ((size_t)b * L_ + l0) * D_ + (col & 63);
    float* obase = o_out + (size_t)mb * 256 + col;

    float4 p[8];
    #pragma unroll
    for (int i = 0; i < 8; i++)
        p[i] = *(const float4*)(pbase + (size_t)(l0 - 7 + i) * 256);

    #pragma unroll
    for (int r = 0; r < RPT; r++) {
        const float4 w0 = *(const float4*)(wbase + r * 8);
        const float4 w1 = *(const float4*)(wbase + r * 8 + 4);
        const float4 rv = *(const float4*)(rbase + (size_t)r * D_);

        float4 acc;
        acc.x = bi.x + rv.x; acc.y = bi.y + rv.y;
        acc.z = bi.z + rv.z; acc.w = bi.w + rv.w;
        const float wj[8] = { w0.x, w0.y, w0.z, w0.w, w1.x, w1.y, w1.z, w1.w };
        #pragma unroll
        for (int j = 0; j < 8; j++) {
            const float4 pv = p[7 - j];
            acc.x = fmaf(wj[j], pv.x, acc.x);
            acc.y = fmaf(wj[j], pv.y, acc.y);
            acc.z = fmaf(wj[j], pv.z, acc.z);
            acc.w = fmaf(wj[j], pv.w, acc.w);
        }
        __stcs((float4*)(obase + (size_t)r * 256), acc);

        if (r < RPT - 1) {
            #pragma unroll
            for (int i = 0; i < 7; i++) p[i] = p[i + 1];
            p[7] = *(const float4*)(pbase + (size_t)(l0 + r + 1) * 256);
        }
    }
}

// =====================================================================
// launch: round-12 DAG (proven best, 63.5us): fill recorded FIRST on s2,
// gemm128 on s3, combine after both on capture stream. No priorities.
// =====================================================================
static cudaStream_t g_s2 = 0, g_s3 = 0;
static cudaEvent_t  g_fork = 0, g_j2 = 0, g_j3 = 0;
static struct StreamInit {
    StreamInit() {
        cudaStreamCreateWithFlags(&g_s2, cudaStreamNonBlocking);
        cudaStreamCreateWithFlags(&g_s3, cudaStreamNonBlocking);
        cudaEventCreateWithFlags(&g_fork, cudaEventDisableTiming);
        cudaEventCreateWithFlags(&g_j2, cudaEventDisableTiming);
        cudaEventCreateWithFlags(&g_j3, cudaEventDisableTiming);
    }
} g_stream_init;

extern "C" void kernel_launch(void* const* d_in, const int* in_sizes, int n_in,
                              void* d_out, int out_size)
{
    const float* inp  = (const float*)d_in[0];
    const float* W    = (const float*)d_in[1];
    const float* bias = (const float*)d_in[2];
    // d_in[3] = masks : compile-time structure, unused

    float* out  = (float*)d_out;           // o : (16, 1008, 4, 64)
    float* attn = out + O_ELEMS;           // attn_stack : (16, 3, 1024, 1024)

    cudaEventRecord(g_fork, 0);
    cudaStreamWaitEvent(g_s2, g_fork, 0);
    cudaStreamWaitEvent(g_s3, g_fork, 0);

    fill_kernel<<<(B_ * L_) / 8, 256, 0, g_s2>>>(inp, attn);
    gemmP_kernel<<<dim3((B_ * L_) / GBM, 256 / GBN), 256, 0, g_s3>>>(inp, W);

    cudaEventRecord(g_j2, g_s2);
    cudaEventRecord(g_j3, g_s3);
    cudaStreamWaitEvent(0, g_j2, 0);
    cudaStreamWaitEvent(0, g_j3, 0);

    combine_kernel<<<(B_ * LQ_ / RPT) / 4, 256>>>(inp, bias, out);
}